// round 9
// baseline (speedup 1.0000x reference)
#include <cuda_runtime.h>
#include <cuda_bf16.h>
#include <cstdint>

constexpr int Bdim = 64;
constexpr int Nseq = 512;
constexpr int E    = 128;
constexpr int D    = 128;
constexpr int H    = 4;

// ---------------- scratch (allocation-free) ----------------
__device__ __nv_bfloat16 g_xh [(size_t)Bdim*Nseq*E];
__device__ __nv_bfloat16 g_xl [(size_t)Bdim*Nseq*E];
__device__ __nv_bfloat16 g_WTh[12 * 128 * 128];          // [which*4+h][d][e] (transposed)
__device__ __nv_bfloat16 g_WTl[12 * 128 * 128];
__device__ __nv_bfloat16 g_W1Th[128 * 512];              // [e_out][k]
__device__ __nv_bfloat16 g_W1Tl[128 * 512];
__device__ __nv_bfloat16 g_W2Th[128 * 128];
__device__ __nv_bfloat16 g_W2Tl[128 * 128];
__device__ __nv_bfloat16 g_Qh[(size_t)Bdim*H*Nseq*D];
__device__ __nv_bfloat16 g_Ql[(size_t)Bdim*H*Nseq*D];
__device__ __nv_bfloat16 g_Kh[(size_t)Bdim*H*Nseq*D];
__device__ __nv_bfloat16 g_Kl[(size_t)Bdim*H*Nseq*D];
__device__ __nv_bfloat16 g_Vh[(size_t)Bdim*H*Nseq*E];    // [bh][n][e]
__device__ __nv_bfloat16 g_Vl[(size_t)Bdim*H*Nseq*E];
__device__ __nv_bfloat16 g_Vth[(size_t)Bdim*H*E*Nseq];   // [bh][e][n]
__device__ __nv_bfloat16 g_Vtl[(size_t)Bdim*H*E*Nseq];
__device__ float         g_S [(size_t)Bdim*H*Nseq*Nseq]; // fp32 scores
__device__ __nv_bfloat16 g_Ph[(size_t)Bdim*H*Nseq*Nseq];
__device__ __nv_bfloat16 g_Pl[(size_t)Bdim*H*Nseq*Nseq];
__device__ __nv_bfloat16 g_Ah[(size_t)Bdim*Nseq*H*E];    // [B,N,512] concat
__device__ __nv_bfloat16 g_Al[(size_t)Bdim*Nseq*H*E];
__device__ __nv_bfloat16 g_H1h[(size_t)Bdim*Nseq*E];
__device__ __nv_bfloat16 g_H1l[(size_t)Bdim*Nseq*E];

// ======================= mma.sync machinery =======================
__device__ __forceinline__ void ldsm_x4(uint32_t r[4], const void* p) {
    uint32_t addr = (uint32_t)__cvta_generic_to_shared(p);
    asm volatile("ldmatrix.sync.aligned.m8n8.x4.shared.b16 {%0,%1,%2,%3}, [%4];"
                 : "=r"(r[0]), "=r"(r[1]), "=r"(r[2]), "=r"(r[3]) : "r"(addr));
}
__device__ __forceinline__ void mma16816(float c[4], const uint32_t a[4], const uint32_t b[2]) {
    asm volatile("mma.sync.aligned.m16n8k16.row.col.f32.bf16.bf16.f32 "
                 "{%0,%1,%2,%3}, {%4,%5,%6,%7}, {%8,%9}, {%0,%1,%2,%3};"
                 : "+f"(c[0]), "+f"(c[1]), "+f"(c[2]), "+f"(c[3])
                 : "r"(a[0]), "r"(a[1]), "r"(a[2]), "r"(a[3]), "r"(b[0]), "r"(b[1]));
}
// smem plane: 128 rows x 32 bf16 (64B rows), 16B chunks XOR-swizzled
__device__ __forceinline__ int sw_idx(int row, int seg) {
    return row * 32 + ((seg ^ ((row >> 1) & 3)) << 3);
}
__device__ __forceinline__ void cp_plane(__nv_bfloat16* dst, const __nv_bfloat16* src,
                                         int ld, int kc, int tid)
{
    #pragma unroll
    for (int s = 0; s < 2; s++) {
        int idx = tid + s * 256;
        int row = idx >> 2, seg = idx & 3;
        uint32_t d = (uint32_t)__cvta_generic_to_shared(dst + sw_idx(row, seg));
        const __nv_bfloat16* g = src + (size_t)row * ld + kc + seg * 8;
        asm volatile("cp.async.cg.shared.global [%0], [%1], 16;" :: "r"(d), "l"(g));
    }
}
__device__ __forceinline__ void load_a_frag(uint32_t a[4][4], const __nv_bfloat16* plane,
                                            int m0, int seg_base, int lane)
{
    const int r = lane & 15, half = lane >> 4;
    #pragma unroll
    for (int t = 0; t < 4; t++)
        ldsm_x4(a[t], plane + sw_idx(m0 + t * 16 + r, seg_base + half));
}
__device__ __forceinline__ void load_b_frag(uint32_t b[4][2], const __nv_bfloat16* plane,
                                            int n0, int seg_base, int lane)
{
    const int r = lane & 15, half = lane >> 4;
    #pragma unroll
    for (int p = 0; p < 2; p++) {
        uint32_t t[4];
        ldsm_x4(t, plane + sw_idx(n0 + p * 16 + r, seg_base + half));
        b[2*p][0]   = t[0];
        b[2*p+1][0] = t[1];
        b[2*p][1]   = t[2];
        b[2*p+1][1] = t[3];
    }
}
__device__ __forceinline__ void mma_all(float acc[4][4][4], const uint32_t a[4][4],
                                        const uint32_t b[4][2])
{
    #pragma unroll
    for (int mt = 0; mt < 4; mt++)
        #pragma unroll
        for (int nt = 0; nt < 4; nt++)
            mma16816(acc[mt][nt], a[mt], b[nt]);
}

// ---------------------------------------------------------------------------
// Split-bf16 (3-product) 128x128 GEMM core, cp.async 3-stage pipeline.
// A: [128 m][K] K-major (hi/lo). B: [128 n][K] K-major (hi/lo).
// sm: 3 stages x 4 planes x 4096 bf16 = 96KB dynamic smem.
// Single __syncthreads per K-chunk; trailing sync protects smem-reuse epilogues.
// ---------------------------------------------------------------------------
__device__ __forceinline__ void ld_stage(__nv_bfloat16* st,
                                         const __nv_bfloat16* Ah, const __nv_bfloat16* Al, int lda,
                                         const __nv_bfloat16* Bh, const __nv_bfloat16* Bl, int ldb,
                                         int kc, int tid)
{
    cp_plane(st + 0*4096, Ah, lda, kc, tid);
    cp_plane(st + 1*4096, Al, lda, kc, tid);
    cp_plane(st + 2*4096, Bh, ldb, kc, tid);
    cp_plane(st + 3*4096, Bl, ldb, kc, tid);
    asm volatile("cp.async.commit_group;");
}

__device__ __forceinline__ void mma_core(
                         const __nv_bfloat16* __restrict__ Ah,
                         const __nv_bfloat16* __restrict__ Al, int lda,
                         const __nv_bfloat16* __restrict__ Bh,
                         const __nv_bfloat16* __restrict__ Bl, int ldb,
                         int K, __nv_bfloat16* sm, float acc[4][4][4])
{
    const int tid = threadIdx.x, lane = tid & 31, wid = tid >> 5;
    const int m0 = (wid >> 2) * 64, n0 = (wid & 3) * 32;

    #pragma unroll
    for (int mt = 0; mt < 4; mt++)
        #pragma unroll
        for (int nt = 0; nt < 4; nt++)
            #pragma unroll
            for (int q = 0; q < 4; q++) acc[mt][nt][q] = 0.f;

    const int NC = K >> 5;
    ld_stage(sm, Ah, Al, lda, Bh, Bl, ldb, 0, tid);
    if (NC > 1) ld_stage(sm + 16384, Ah, Al, lda, Bh, Bl, ldb, 32, tid);

    int stage = 0;
    for (int c = 0; c < NC; c++) {
        if (c + 1 < NC) asm volatile("cp.async.wait_group 1;");
        else            asm volatile("cp.async.wait_group 0;");
        __syncthreads();
        if (c + 2 < NC) {
            int ps = stage + 2; if (ps >= 3) ps -= 3;
            ld_stage(sm + ps * 16384, Ah, Al, lda, Bh, Bl, ldb, (c + 2) * 32, tid);
        }
        __nv_bfloat16* st = sm + stage * 16384;
        #pragma unroll
        for (int ks = 0; ks < 2; ks++) {
            const int seg = ks * 2;
            uint32_t a[4][4];
            uint32_t bh_[4][2];
            uint32_t bl_[4][2];
            load_a_frag(a, st + 0*4096, m0, seg, lane);   // A hi
            load_b_frag(bh_, st + 2*4096, n0, seg, lane); // B hi
            mma_all(acc, a, bh_);                         // hi*hi
            load_b_frag(bl_, st + 3*4096, n0, seg, lane); // B lo
            mma_all(acc, a, bl_);                         // hi*lo
            load_a_frag(a, st + 1*4096, m0, seg, lane);   // A lo (overwrite)
            mma_all(acc, a, bh_);                         // lo*hi (B hi in regs)
        }
        if (++stage == 3) stage = 0;
    }
    __syncthreads();   // protect smem-reusing epilogues (LN buffers)
}

// LayerNorm over 128 cols in mma fragment layout. lnbuf >= 1280 floats.
__device__ __forceinline__ void ln_mma(float acc[4][4][4], float* lnbuf)
{
    float* lnS = lnbuf;
    float* lnQ = lnbuf + 512;
    float* mrs = lnbuf + 1024;
    const int tid = threadIdx.x, lane = tid & 31, wid = tid >> 5;
    const int wn = wid & 3, m0 = (wid >> 2) * 64;
    const int rr = lane >> 2, cg = lane & 3;

    #pragma unroll
    for (int mt = 0; mt < 4; mt++)
        #pragma unroll
        for (int half = 0; half < 2; half++) {
            float s = 0.f, q = 0.f;
            #pragma unroll
            for (int nt = 0; nt < 4; nt++) {
                float v0 = acc[mt][nt][2*half], v1 = acc[mt][nt][2*half+1];
                s += v0 + v1; q += v0 * v0 + v1 * v1;
            }
            s += __shfl_xor_sync(0xffffffffu, s, 1);
            s += __shfl_xor_sync(0xffffffffu, s, 2);
            q += __shfl_xor_sync(0xffffffffu, q, 1);
            q += __shfl_xor_sync(0xffffffffu, q, 2);
            if (cg == 0) {
                int row = m0 + mt * 16 + half * 8 + rr;
                lnS[row * 4 + wn] = s;
                lnQ[row * 4 + wn] = q;
            }
        }
    __syncthreads();
    if (tid < 128) {
        float s = lnS[tid*4] + lnS[tid*4+1] + lnS[tid*4+2] + lnS[tid*4+3];
        float q = lnQ[tid*4] + lnQ[tid*4+1] + lnQ[tid*4+2] + lnQ[tid*4+3];
        float mean = s * (1.0f / 128.0f);
        float var  = q * (1.0f / 128.0f) - mean * mean;
        mrs[tid]       = mean;
        mrs[128 + tid] = rsqrtf(var + 1e-5f);
    }
    __syncthreads();
    #pragma unroll
    for (int mt = 0; mt < 4; mt++)
        #pragma unroll
        for (int half = 0; half < 2; half++) {
            int row = m0 + mt * 16 + half * 8 + rr;
            float mu = mrs[row], rs = mrs[128 + row];
            #pragma unroll
            for (int nt = 0; nt < 4; nt++) {
                acc[mt][nt][2*half]   = (acc[mt][nt][2*half]   - mu) * rs;
                acc[mt][nt][2*half+1] = (acc[mt][nt][2*half+1] - mu) * rs;
            }
        }
}

__device__ __forceinline__ uint32_t pack_hi2(float v0, float v1, uint32_t& lo)
{
    __nv_bfloat16 h0 = __float2bfloat16(v0), h1 = __float2bfloat16(v1);
    __nv_bfloat16 l0 = __float2bfloat16(v0 - __bfloat162float(h0));
    __nv_bfloat16 l1 = __float2bfloat16(v1 - __bfloat162float(h1));
    lo = (uint32_t)__bfloat16_as_ushort(l0) | ((uint32_t)__bfloat16_as_ushort(l1) << 16);
    return (uint32_t)__bfloat16_as_ushort(h0) | ((uint32_t)__bfloat16_as_ushort(h1) << 16);
}

__device__ __forceinline__ void store_hilo(const float acc[4][4][4],
                                           __nv_bfloat16* oh, __nv_bfloat16* ol,
                                           int ldc)
{
    const int lane = threadIdx.x & 31, wid = threadIdx.x >> 5;
    const int m0 = (wid >> 2) * 64, n0 = (wid & 3) * 32;
    const int rr = lane >> 2, cg = lane & 3;
    #pragma unroll
    for (int mt = 0; mt < 4; mt++)
        #pragma unroll
        for (int half = 0; half < 2; half++) {
            int row = m0 + mt * 16 + half * 8 + rr;
            #pragma unroll
            for (int nt = 0; nt < 4; nt++) {
                int c = n0 + nt * 8 + 2 * cg;
                uint32_t lo;
                uint32_t hi = pack_hi2(acc[mt][nt][2*half], acc[mt][nt][2*half+1], lo);
                *reinterpret_cast<uint32_t*>(oh + (size_t)row * ldc + c) = hi;
                *reinterpret_cast<uint32_t*>(ol + (size_t)row * ldc + c) = lo;
            }
        }
}

// ======================= prep kernels =======================
__global__ __launch_bounds__(256) void split_x_kernel(const float* __restrict__ x)
{
    const size_t i4 = (size_t)blockIdx.x * 256 + threadIdx.x;
    float4 v = *reinterpret_cast<const float4*>(x + i4 * 4);
    uint32_t l0, l1;
    uint32_t h0 = pack_hi2(v.x, v.y, l0);
    uint32_t h1 = pack_hi2(v.z, v.w, l1);
    *reinterpret_cast<uint2*>(g_xh + i4 * 4) = make_uint2(h0, h1);
    *reinterpret_cast<uint2*>(g_xl + i4 * 4) = make_uint2(l0, l1);
}

// transpose+split a [R,C] fp32 matrix -> dst hi/lo [C,R] bf16
__device__ __forceinline__ void transplit_tile(const float* src, __nv_bfloat16* dh,
                                               __nv_bfloat16* dl, int R, int C,
                                               int r0, int c0)
{
    __shared__ float t[32][33];
    const int tid = threadIdx.x;
    #pragma unroll
    for (int s = 0; s < 4; s++) {
        int idx = tid + s * 256;
        int r = idx >> 5, c = idx & 31;
        t[r][c] = src[(size_t)(r0 + r) * C + c0 + c];
    }
    __syncthreads();
    #pragma unroll
    for (int s = 0; s < 4; s++) {
        int idx = tid + s * 256;
        int co = idx >> 5, ro = idx & 31;
        float v = t[ro][co];
        __nv_bfloat16 h = __float2bfloat16(v);
        dh[(size_t)(c0 + co) * R + r0 + ro] = h;
        dl[(size_t)(c0 + co) * R + r0 + ro] = __float2bfloat16(v - __bfloat162float(h));
    }
}

__global__ __launch_bounds__(256) void qkv_prep_kernel(
    const float* __restrict__ Wq, const float* __restrict__ Wk, const float* __restrict__ Wv)
{
    const int midx = blockIdx.x;           // which*4 + h
    const int which = midx >> 2, h = midx & 3;
    const float* src = (which == 0 ? Wq : (which == 1 ? Wk : Wv)) + (size_t)h * 128 * 128;
    transplit_tile(src, g_WTh + (size_t)midx * 16384, g_WTl + (size_t)midx * 16384,
                   128, 128, blockIdx.y * 32, blockIdx.z * 32);
}
__global__ __launch_bounds__(256) void w1_prep_kernel(const float* __restrict__ W1)
{
    transplit_tile(W1, g_W1Th, g_W1Tl, 512, 128, blockIdx.x * 32, blockIdx.y * 32);
}
__global__ __launch_bounds__(256) void w2_prep_kernel(const float* __restrict__ W2)
{
    transplit_tile(W2, g_W2Th, g_W2Tl, 128, 128, blockIdx.x * 32, blockIdx.y * 32);
}

// ======================= main kernels =======================
extern __shared__ __nv_bfloat16 dynsm[];

// QKV: grid (256, H, 3)
__global__ __launch_bounds__(256) void qkv_mma(
    const float* __restrict__ bq, const float* __restrict__ bk, const float* __restrict__ bv)
{
    const int rowBase = blockIdx.x * 128;
    const int h = blockIdx.y, which = blockIdx.z;
    const int midx = which * 4 + h;
    const float* bias = (which == 0 ? bq : (which == 1 ? bk : bv)) + (size_t)h * 128;

    float acc[4][4][4];
    mma_core(g_xh + (size_t)rowBase * E, g_xl + (size_t)rowBase * E, E,
             g_WTh + (size_t)midx * 16384, g_WTl + (size_t)midx * 16384, E,
             E, dynsm, acc);

    const int lane = threadIdx.x & 31, wid = threadIdx.x >> 5;
    const int n0 = (wid & 3) * 32, cg = lane & 3;
    #pragma unroll
    for (int nt = 0; nt < 4; nt++) {
        float2 bv2 = *reinterpret_cast<const float2*>(bias + n0 + nt * 8 + 2 * cg);
        #pragma unroll
        for (int mt = 0; mt < 4; mt++) {
            acc[mt][nt][0] += bv2.x; acc[mt][nt][1] += bv2.y;
            acc[mt][nt][2] += bv2.x; acc[mt][nt][3] += bv2.y;
        }
    }
    ln_mma(acc, (float*)dynsm);

    const int b = rowBase >> 9, nBase = rowBase & 511;
    const int bh = b * H + h;
    const size_t off = ((size_t)bh * Nseq + nBase) * 128;
    __nv_bfloat16* oh = (which == 0 ? g_Qh : (which == 1 ? g_Kh : g_Vh)) + off;
    __nv_bfloat16* ol = (which == 0 ? g_Ql : (which == 1 ? g_Kl : g_Vl)) + off;
    store_hilo(acc, oh, ol, 128);
}

// V transpose: grid (256, 4, 16)
__global__ __launch_bounds__(256) void vtrans_kernel()
{
    __shared__ __nv_bfloat16 th[32][33], tl[32][33];
    const int bh = blockIdx.x, e0 = blockIdx.y * 32, n0 = blockIdx.z * 32;
    const int tid = threadIdx.x;
    const size_t inBase = ((size_t)bh * Nseq + n0) * E + e0;
    #pragma unroll
    for (int s = 0; s < 4; s++) {
        int idx = tid + s * 256;
        int r = idx >> 5, c = idx & 31;
        th[r][c] = g_Vh[inBase + (size_t)r * E + c];
        tl[r][c] = g_Vl[inBase + (size_t)r * E + c];
    }
    __syncthreads();
    const size_t outBase = ((size_t)bh * E + e0) * Nseq + n0;
    #pragma unroll
    for (int s = 0; s < 4; s++) {
        int idx = tid + s * 256;
        int r = idx >> 5, c = idx & 31;
        g_Vth[outBase + (size_t)r * Nseq + c] = th[c][r];
        g_Vtl[outBase + (size_t)r * Nseq + c] = tl[c][r];
    }
}

// scores = Q K^T -> fp32 S. grid (4, 4, 256)
__global__ __launch_bounds__(256) void scores_mma()
{
    const int bh = blockIdx.z;
    const size_t rowBase = blockIdx.x * 128, colBase = blockIdx.y * 128;
    float acc[4][4][4];
    mma_core(g_Qh + ((size_t)bh * Nseq + rowBase) * D,
             g_Ql + ((size_t)bh * Nseq + rowBase) * D, D,
             g_Kh + ((size_t)bh * Nseq + colBase) * D,
             g_Kl + ((size_t)bh * Nseq + colBase) * D, D, D, dynsm, acc);

    float* Cout = g_S + (size_t)bh * Nseq * Nseq + rowBase * Nseq + colBase;
    const int lane = threadIdx.x & 31, wid = threadIdx.x >> 5;
    const int m0 = (wid >> 2) * 64, n0 = (wid & 3) * 32;
    const int rr = lane >> 2, cg = lane & 3;
    #pragma unroll
    for (int mt = 0; mt < 4; mt++)
        #pragma unroll
        for (int half = 0; half < 2; half++) {
            int r = m0 + mt * 16 + half * 8 + rr;
            #pragma unroll
            for (int nt = 0; nt < 4; nt++) {
                int c = n0 + nt * 8 + 2 * cg;
                *reinterpret_cast<float2*>(Cout + (size_t)r * Nseq + c) =
                    make_float2(acc[mt][nt][2*half], acc[mt][nt][2*half+1]);
            }
        }
}

// batch-axis softmax. grid (4096)
__global__ __launch_bounds__(256) void softmax_kernel()
{
    const size_t idx = (size_t)blockIdx.x * 256 + threadIdx.x;
    const size_t stride = (size_t)H * Nseq * Nseq;
    float v[64];
    float mx = -1e30f;
    #pragma unroll
    for (int b = 0; b < 64; b++) {
        float t = g_S[(size_t)b * stride + idx] * (1.0f / 11.0f);
        v[b] = t;
        mx = fmaxf(mx, t);
    }
    float s = 0.f;
    #pragma unroll
    for (int b = 0; b < 64; b++) { float e = __expf(v[b] - mx); v[b] = e; s += e; }
    const float inv = 1.0f / s;
    #pragma unroll
    for (int b = 0; b < 64; b++) {
        float p = v[b] * inv;
        __nv_bfloat16 hp = __float2bfloat16(p);
        __nv_bfloat16 lp = __float2bfloat16(p - __bfloat162float(hp));
        g_Ph[(size_t)b * stride + idx] = hp;
        g_Pl[(size_t)b * stride + idx] = lp;
    }
}

// A = P V -> hi/lo concat layout. grid (4, 1, 256)
__global__ __launch_bounds__(256) void av_mma()
{
    const int bh = blockIdx.z, b = bh >> 2, h = bh & 3;
    const size_t rowBase = blockIdx.x * 128;
    float acc[4][4][4];
    mma_core(g_Ph + ((size_t)bh * Nseq + rowBase) * Nseq,
             g_Pl + ((size_t)bh * Nseq + rowBase) * Nseq, Nseq,
             g_Vth + (size_t)bh * E * Nseq,
             g_Vtl + (size_t)bh * E * Nseq, Nseq, Nseq, dynsm, acc);
    const size_t off = ((size_t)b * Nseq + rowBase) * (H * E) + (size_t)h * E;
    store_hilo(acc, g_Ah + off, g_Al + off, H * E);
}

// h1 = relu(A @ W1 + b1) -> hi/lo. grid (256)
__global__ __launch_bounds__(256) void mlp1_mma(const float* __restrict__ b1)
{
    const int rowBase = blockIdx.x * 128;
    float acc[4][4][4];
    mma_core(g_Ah + (size_t)rowBase * (H * E), g_Al + (size_t)rowBase * (H * E), H * E,
             g_W1Th, g_W1Tl, H * E, H * E, dynsm, acc);

    const int lane = threadIdx.x & 31, wid = threadIdx.x >> 5;
    const int n0 = (wid & 3) * 32, cg = lane & 3;
    #pragma unroll
    for (int nt = 0; nt < 4; nt++) {
        float2 bv2 = *reinterpret_cast<const float2*>(b1 + n0 + nt * 8 + 2 * cg);
        #pragma unroll
        for (int mt = 0; mt < 4; mt++) {
            acc[mt][nt][0] = fmaxf(acc[mt][nt][0] + bv2.x, 0.f);
            acc[mt][nt][1] = fmaxf(acc[mt][nt][1] + bv2.y, 0.f);
            acc[mt][nt][2] = fmaxf(acc[mt][nt][2] + bv2.x, 0.f);
            acc[mt][nt][3] = fmaxf(acc[mt][nt][3] + bv2.y, 0.f);
        }
    }
    store_hilo(acc, g_H1h + (size_t)rowBase * E, g_H1l + (size_t)rowBase * E, E);
}

// out = LN(x + relu(h1 @ W2 + b2)) * gamma + beta. grid (256)
__global__ __launch_bounds__(256) void mlp2_mma(
    const float* __restrict__ x, const float* __restrict__ b2,
    const float* __restrict__ gamma, const float* __restrict__ beta,
    float* __restrict__ out)
{
    const int rowBase = blockIdx.x * 128;
    float acc[4][4][4];
    mma_core(g_H1h + (size_t)rowBase * E, g_H1l + (size_t)rowBase * E, E,
             g_W2Th, g_W2Tl, E, E, dynsm, acc);

    const int lane = threadIdx.x & 31, wid = threadIdx.x >> 5;
    const int m0 = (wid >> 2) * 64, n0 = (wid & 3) * 32;
    const int rr = lane >> 2, cg = lane & 3;
    #pragma unroll
    for (int nt = 0; nt < 4; nt++) {
        const int c = n0 + nt * 8 + 2 * cg;
        float2 bv2 = *reinterpret_cast<const float2*>(b2 + c);
        #pragma unroll
        for (int mt = 0; mt < 4; mt++)
            #pragma unroll
            for (int half = 0; half < 2; half++) {
                int row = rowBase + m0 + mt * 16 + half * 8 + rr;
                float2 xv = *reinterpret_cast<const float2*>(x + (size_t)row * E + c);
                acc[mt][nt][2*half]   = fmaxf(acc[mt][nt][2*half]   + bv2.x, 0.f) + xv.x;
                acc[mt][nt][2*half+1] = fmaxf(acc[mt][nt][2*half+1] + bv2.y, 0.f) + xv.y;
            }
    }

    ln_mma(acc, (float*)dynsm);

    #pragma unroll
    for (int nt = 0; nt < 4; nt++) {
        const int c = n0 + nt * 8 + 2 * cg;
        float2 gv = *reinterpret_cast<const float2*>(gamma + c);
        float2 ev = *reinterpret_cast<const float2*>(beta + c);
        #pragma unroll
        for (int mt = 0; mt < 4; mt++)
            #pragma unroll
            for (int half = 0; half < 2; half++) {
                int row = rowBase + m0 + mt * 16 + half * 8 + rr;
                float o0 = acc[mt][nt][2*half]   * gv.x + ev.x;
                float o1 = acc[mt][nt][2*half+1] * gv.y + ev.y;
                *reinterpret_cast<float2*>(out + (size_t)row * E + c) = make_float2(o0, o1);
            }
    }
}

// ---------------------------------------------------------------------------
extern "C" void kernel_launch(void* const* d_in, const int* in_sizes, int n_in,
                              void* d_out, int out_size)
{
    const float* x     = (const float*)d_in[0];
    const float* Wq    = (const float*)d_in[1];
    const float* bq    = (const float*)d_in[2];
    const float* Wk    = (const float*)d_in[3];
    const float* bk    = (const float*)d_in[4];
    const float* Wv    = (const float*)d_in[5];
    const float* bv    = (const float*)d_in[6];
    const float* W1    = (const float*)d_in[7];
    const float* b1    = (const float*)d_in[8];
    const float* W2    = (const float*)d_in[9];
    const float* b2    = (const float*)d_in[10];
    const float* gamma = (const float*)d_in[11];
    const float* beta  = (const float*)d_in[12];
    float* out = (float*)d_out;

    const int SMEM = 3 * 4 * 4096 * (int)sizeof(__nv_bfloat16);   // 96KB
    cudaFuncSetAttribute(qkv_mma,    cudaFuncAttributeMaxDynamicSharedMemorySize, SMEM);
    cudaFuncSetAttribute(scores_mma, cudaFuncAttributeMaxDynamicSharedMemorySize, SMEM);
    cudaFuncSetAttribute(av_mma,     cudaFuncAttributeMaxDynamicSharedMemorySize, SMEM);
    cudaFuncSetAttribute(mlp1_mma,   cudaFuncAttributeMaxDynamicSharedMemorySize, SMEM);
    cudaFuncSetAttribute(mlp2_mma,   cudaFuncAttributeMaxDynamicSharedMemorySize, SMEM);

    dim3 blk(256);
    split_x_kernel <<<dim3(4096), blk>>>(x);
    qkv_prep_kernel<<<dim3(12, 4, 4), blk>>>(Wq, Wk, Wv);
    w1_prep_kernel <<<dim3(16, 4), blk>>>(W1);
    w2_prep_kernel <<<dim3(4, 4), blk>>>(W2);
    qkv_mma        <<<dim3(256, 4, 3), blk, SMEM>>>(bq, bk, bv);
    vtrans_kernel  <<<dim3(256, 4, 16), blk>>>();
    scores_mma     <<<dim3(4, 4, 256), blk, SMEM>>>();
    softmax_kernel <<<dim3(4096), blk>>>();
    av_mma         <<<dim3(4, 1, 256), blk, SMEM>>>();
    mlp1_mma       <<<dim3(256), blk, SMEM>>>(b1);
    mlp2_mma       <<<dim3(256), blk, SMEM>>>(x, b2, gamma, beta, out);
}